// round 1
// baseline (speedup 1.0000x reference)
#include <cuda_runtime.h>
#include <cuda_bf16.h>
#include <math.h>

#define MAXN 100000
#define MAXE 1600000
#define DIN 32
#define DE 16
#define DEMB 64
#define DGIN 96
#define NH 4
#define HC 16

// ---------------- scratch (static device globals; no allocation) -------------
__device__ float g_h[(size_t)MAXN * DEMB];
__device__ float g_xp[(size_t)MAXN * DEMB];
__device__ float g_out[(size_t)MAXN * DEMB];
__device__ float g_asrc[MAXN * NH];
__device__ float g_adst[MAXN * NH];
__device__ float g_expsum[MAXN * NH];
__device__ float g_aedge[(size_t)MAXE * NH];
__device__ float g_loopsum[MAXN * DE];
__device__ float g_loopattr[MAXN * DE];
__device__ float g_deg[MAXN];
__device__ float g_weatt[DE * NH];
__device__ float g_gsum[256 * DEMB];
__device__ float g_gcnt[256];

__device__ __forceinline__ void red_add_v4(float* addr, float a, float b, float c, float d) {
    asm volatile("red.relaxed.gpu.global.add.v4.f32 [%0], {%1,%2,%3,%4};"
                 :: "l"(addr), "f"(a), "f"(b), "f"(c), "f"(d) : "memory");
}

__device__ __forceinline__ float leaky(float a) { return a > 0.f ? a : 0.2f * a; }

// ---------------- degree + self-loop edge-attr mean --------------------------
__global__ void k_deg_loop(const int* __restrict__ dst, const float* __restrict__ eattr, int ne) {
    int e = blockIdx.x * blockDim.x + threadIdx.x;
    if (e >= ne) return;
    int d = dst[e];
    atomicAdd(&g_deg[d], 1.f);
    const float4* ea = (const float4*)(eattr + (size_t)e * DE);
    float* lp = g_loopsum + (size_t)d * DE;
#pragma unroll
    for (int k = 0; k < 4; k++) {
        float4 v = ea[k];
        red_add_v4(lp + 4 * k, v.x, v.y, v.z, v.w);
    }
}

__global__ void k_loopattr(int n) {
    int i = blockIdx.x * blockDim.x + threadIdx.x;
    if (i >= n * DE) return;
    float dg = g_deg[i >> 4];
    g_loopattr[i] = g_loopsum[i] / fmaxf(dg, 1.f);
}

// ---------------- node_in_fc: h = relu(x @ W_in + b_in) ----------------------
__global__ void k_hin(const float* __restrict__ x, const float* __restrict__ W,
                      const float* __restrict__ b, int n_nodes) {
    __shared__ float sW[DIN * DEMB];
    __shared__ float sB[DEMB];
    __shared__ float sX[8][DIN];
    int tid = threadIdx.x;
    for (int i = tid; i < DIN * DEMB; i += 256) sW[i] = W[i];
    if (tid < DEMB) sB[tid] = b[tid];
    __syncthreads();
    int w = tid >> 5, lane = tid & 31;
    int n = blockIdx.x * 8 + w;
    if (n >= n_nodes) return;
    sX[w][lane] = x[(size_t)n * DIN + lane];
    __syncwarp();
    float a0 = sB[lane], a1 = sB[lane + 32];
#pragma unroll
    for (int k = 0; k < DIN; k++) {
        float xv = sX[w][k];
        a0 = fmaf(xv, sW[k * 64 + lane], a0);
        a1 = fmaf(xv, sW[k * 64 + lane + 32], a1);
    }
    g_h[(size_t)n * 64 + lane] = fmaxf(a0, 0.f);
    g_h[(size_t)n * 64 + lane + 32] = fmaxf(a1, 0.f);
}

// ---------------- per-layer: weatt[d][h] = sum_c We[d, h*16+c] * attE[h,c] ---
__global__ void k_weatt(const float* __restrict__ We, const float* __restrict__ attE) {
    int t = threadIdx.x;           // 64 threads
    int d = t >> 2, h = t & 3;
    float s = 0.f;
#pragma unroll
    for (int c = 0; c < HC; c++) s = fmaf(We[d * 64 + h * 16 + c], attE[h * 16 + c], s);
    g_weatt[d * 4 + h] = s;
}

// ---------------- a_edge for real edges --------------------------------------
__global__ void k_aedge(const float* __restrict__ eattr, int ne) {
    __shared__ float sWA[DE * NH];
    if (threadIdx.x < DE * NH) sWA[threadIdx.x] = g_weatt[threadIdx.x];
    __syncthreads();
    int e = blockIdx.x * blockDim.x + threadIdx.x;
    if (e >= ne) return;
    const float* ea = eattr + (size_t)e * DE;
    float a0 = 0.f, a1 = 0.f, a2 = 0.f, a3 = 0.f;
#pragma unroll
    for (int d = 0; d < DE; d++) {
        float v = ea[d];
        a0 = fmaf(v, sWA[d * 4 + 0], a0);
        a1 = fmaf(v, sWA[d * 4 + 1], a1);
        a2 = fmaf(v, sWA[d * 4 + 2], a2);
        a3 = fmaf(v, sWA[d * 4 + 3], a3);
    }
    float4* o = (float4*)(g_aedge + (size_t)e * 4);
    *o = make_float4(a0, a1, a2, a3);
}

// ---------------- xp = [x,h] @ Wg ; a_src ; a_dst ----------------------------
__global__ void k_xp(const float* __restrict__ x, int n_nodes,
                     const float* __restrict__ Wg, const float* __restrict__ attS,
                     const float* __restrict__ attD) {
    __shared__ float sW[DGIN * DEMB];   // 24 KB
    __shared__ float sAS[DEMB], sAD[DEMB];
    __shared__ float sGin[4][DGIN];
    int tid = threadIdx.x;
    for (int i = tid; i < DGIN * DEMB; i += 256) sW[i] = Wg[i];
    if (tid < DEMB) { sAS[tid] = attS[tid]; sAD[tid] = attD[tid]; }
    __syncthreads();
    int grp = tid >> 6, col = tid & 63;
    int h = col >> 4;
    int base = blockIdx.x * 32;
    for (int c = 0; c < 8; c++) {
        int n = base + c * 4 + grp;
        if (n < n_nodes) {
            for (int k = col; k < DGIN; k += 64)
                sGin[grp][k] = (k < DIN) ? x[(size_t)n * DIN + k]
                                         : g_h[(size_t)n * 64 + (k - DIN)];
        }
        __syncthreads();
        if (n < n_nodes) {
            float acc = 0.f;
#pragma unroll
            for (int k = 0; k < DGIN; k++) acc = fmaf(sGin[grp][k], sW[k * 64 + col], acc);
            g_xp[(size_t)n * 64 + col] = acc;
            float vs = acc * sAS[col];
            float vd = acc * sAD[col];
#pragma unroll
            for (int o = 8; o; o >>= 1) {
                vs += __shfl_xor_sync(0xffffffffu, vs, o);
                vd += __shfl_xor_sync(0xffffffffu, vd, o);
            }
            if ((col & 15) == 0) {
                g_asrc[n * 4 + h] = vs;
                g_adst[n * 4 + h] = vd;
            }
        }
        __syncthreads();
    }
}

// ---------------- self-loop: init expsum with exp(alpha_self) ----------------
__global__ void k_selfA(int n_nodes) {
    int n = blockIdx.x * blockDim.x + threadIdx.x;
    if (n >= n_nodes) return;
    const float* la = g_loopattr + (size_t)n * DE;
    float a[4];
    float4 as = *(const float4*)(g_asrc + n * 4);
    float4 ad = *(const float4*)(g_adst + n * 4);
    a[0] = as.x + ad.x; a[1] = as.y + ad.y; a[2] = as.z + ad.z; a[3] = as.w + ad.w;
#pragma unroll
    for (int d = 0; d < DE; d++) {
        float v = la[d];
        a[0] = fmaf(v, g_weatt[d * 4 + 0], a[0]);
        a[1] = fmaf(v, g_weatt[d * 4 + 1], a[1]);
        a[2] = fmaf(v, g_weatt[d * 4 + 2], a[2]);
        a[3] = fmaf(v, g_weatt[d * 4 + 3], a[3]);
    }
    float4 ex;
    ex.x = __expf(leaky(a[0])); ex.y = __expf(leaky(a[1]));
    ex.z = __expf(leaky(a[2])); ex.w = __expf(leaky(a[3]));
    *(float4*)(g_expsum + n * 4) = ex;
}

// ---------------- init out numerator with self-loop message ------------------
__global__ void k_selfB(int n_nodes) {
    int i = blockIdx.x * blockDim.x + threadIdx.x;
    if (i >= n_nodes * 64) return;
    int n = i >> 6;
    int h = (i >> 4) & 3;
    g_out[i] = g_xp[i] * g_expsum[n * 4 + h];
}

// ---------------- edge pass 1: accumulate exp sums ---------------------------
__global__ void k_edge_sum(const int* __restrict__ src, const int* __restrict__ dst, int ne) {
    int e = blockIdx.x * blockDim.x + threadIdx.x;
    if (e >= ne) return;
    int s = src[e], d = dst[e];
    float4 as = *(const float4*)(g_asrc + s * 4);
    float4 ad = *(const float4*)(g_adst + d * 4);
    float4 ae = *(const float4*)(g_aedge + (size_t)e * 4);
    float e0 = __expf(leaky(as.x + ad.x + ae.x));
    float e1 = __expf(leaky(as.y + ad.y + ae.y));
    float e2 = __expf(leaky(as.z + ad.z + ae.z));
    float e3 = __expf(leaky(as.w + ad.w + ae.w));
    red_add_v4(g_expsum + d * 4, e0, e1, e2, e3);
}

// ---------------- edge pass 2: accumulate messages (thread = edge*head) ------
__global__ void k_edge_msg(const int* __restrict__ src, const int* __restrict__ dst, int ne) {
    long long t = (long long)blockIdx.x * blockDim.x + threadIdx.x;
    if (t >= (long long)ne * 4) return;
    int e = (int)(t >> 2), h = (int)(t & 3);
    int s = src[e], d = dst[e];
    float a = g_asrc[s * 4 + h] + g_adst[d * 4 + h] + g_aedge[(size_t)e * 4 + h];
    float ex = __expf(leaky(a));
    const float4* xr = (const float4*)(g_xp + (size_t)s * 64 + h * 16);
    float* orow = g_out + (size_t)d * 64 + h * 16;
#pragma unroll
    for (int k = 0; k < 4; k++) {
        float4 v = xr[k];
        red_add_v4(orow + 4 * k, v.x * ex, v.y * ex, v.z * ex, v.w * ex);
    }
}

// ---------------- normalize + bias + LN + ELU -> h ---------------------------
__global__ void k_norm(const float* __restrict__ bg, const float* __restrict__ lng,
                       const float* __restrict__ lnb, int n_nodes) {
    int w = threadIdx.x >> 5, lane = threadIdx.x & 31;
    int n = blockIdx.x * 8 + w;
    if (n >= n_nodes) return;
    float es0 = g_expsum[n * 4 + (lane >> 4)];
    float es1 = g_expsum[n * 4 + 2 + (lane >> 4)];
    float v0 = g_out[(size_t)n * 64 + lane] / es0 + bg[lane];
    float v1 = g_out[(size_t)n * 64 + lane + 32] / es1 + bg[lane + 32];
    float s = v0 + v1;
#pragma unroll
    for (int o = 16; o; o >>= 1) s += __shfl_xor_sync(0xffffffffu, s, o);
    float m = s * (1.f / 64.f);
    float d0 = v0 - m, d1 = v1 - m;
    float q = d0 * d0 + d1 * d1;
#pragma unroll
    for (int o = 16; o; o >>= 1) q += __shfl_xor_sync(0xffffffffu, q, o);
    float rs = rsqrtf(q * (1.f / 64.f) + 1e-5f);
    float y0 = d0 * rs * lng[lane] + lnb[lane];
    float y1 = d1 * rs * lng[lane + 32] + lnb[lane + 32];
    y0 = y0 > 0.f ? y0 : expm1f(y0);
    y1 = y1 > 0.f ? y1 : expm1f(y1);
    g_h[(size_t)n * 64 + lane] = y0;
    g_h[(size_t)n * 64 + lane + 32] = y1;
}

// ---------------- final: node_emb + per-node graph feature + pooled sums -----
__global__ void k_outfc(const float* __restrict__ Wout, const float* __restrict__ bout,
                        const float* __restrict__ lnfg, const float* __restrict__ lnfb,
                        const float* __restrict__ Wgr, const float* __restrict__ bgr,
                        const float* __restrict__ lngg, const float* __restrict__ lngb,
                        const int* __restrict__ batch, float* __restrict__ out_node,
                        int n_nodes) {
    __shared__ float sW1[64 * 64];
    __shared__ float sW2[64 * 64];
    __shared__ float sH[8][64];
    int tid = threadIdx.x;
    for (int i = tid; i < 4096; i += 256) { sW1[i] = Wout[i]; sW2[i] = Wgr[i]; }
    __syncthreads();
    int w = tid >> 5, lane = tid & 31;
    int n = blockIdx.x * 8 + w;
    if (n >= n_nodes) return;
    sH[w][lane] = g_h[(size_t)n * 64 + lane];
    sH[w][lane + 32] = g_h[(size_t)n * 64 + lane + 32];
    __syncwarp();

    // node_emb = LN(relu(h @ Wout + bout))
    {
        float a0 = bout[lane], a1 = bout[lane + 32];
#pragma unroll
        for (int k = 0; k < 64; k++) {
            float hv = sH[w][k];
            a0 = fmaf(hv, sW1[k * 64 + lane], a0);
            a1 = fmaf(hv, sW1[k * 64 + lane + 32], a1);
        }
        a0 = fmaxf(a0, 0.f); a1 = fmaxf(a1, 0.f);
        float s = a0 + a1;
#pragma unroll
        for (int o = 16; o; o >>= 1) s += __shfl_xor_sync(0xffffffffu, s, o);
        float m = s * (1.f / 64.f);
        float d0 = a0 - m, d1 = a1 - m;
        float q = d0 * d0 + d1 * d1;
#pragma unroll
        for (int o = 16; o; o >>= 1) q += __shfl_xor_sync(0xffffffffu, q, o);
        float rs = rsqrtf(q * (1.f / 64.f) + 1e-5f);
        out_node[(size_t)n * 64 + lane] = d0 * rs * lnfg[lane] + lnfb[lane];
        out_node[(size_t)n * 64 + lane + 32] = d1 * rs * lnfg[lane + 32] + lnfb[lane + 32];
    }
    // g = LN(relu(h @ Wgr + bgr)); pooled sum per graph
    {
        float a0 = bgr[lane], a1 = bgr[lane + 32];
#pragma unroll
        for (int k = 0; k < 64; k++) {
            float hv = sH[w][k];
            a0 = fmaf(hv, sW2[k * 64 + lane], a0);
            a1 = fmaf(hv, sW2[k * 64 + lane + 32], a1);
        }
        a0 = fmaxf(a0, 0.f); a1 = fmaxf(a1, 0.f);
        float s = a0 + a1;
#pragma unroll
        for (int o = 16; o; o >>= 1) s += __shfl_xor_sync(0xffffffffu, s, o);
        float m = s * (1.f / 64.f);
        float d0 = a0 - m, d1 = a1 - m;
        float q = d0 * d0 + d1 * d1;
#pragma unroll
        for (int o = 16; o; o >>= 1) q += __shfl_xor_sync(0xffffffffu, q, o);
        float rs = rsqrtf(q * (1.f / 64.f) + 1e-5f);
        float g0 = d0 * rs * lngg[lane] + lngb[lane];
        float g1 = d1 * rs * lngg[lane + 32] + lngb[lane + 32];
        int b = batch[n];
        atomicAdd(&g_gsum[b * 64 + lane], g0);
        atomicAdd(&g_gsum[b * 64 + lane + 32], g1);
        if (lane == 0) atomicAdd(&g_gcnt[b], 1.f);
    }
}

__global__ void k_graphdiv(float* __restrict__ out_graph, int nb) {
    int i = blockIdx.x * blockDim.x + threadIdx.x;
    if (i >= nb * 64) return;
    out_graph[i] = g_gsum[i] / fmaxf(g_gcnt[i >> 6], 1.f);
}

// ============================================================================
extern "C" void kernel_launch(void* const* d_in, const int* in_sizes, int n_in,
                              void* d_out, int out_size) {
    const float* x      = (const float*)d_in[0];
    const int*   ei     = (const int*)d_in[1];
    const float* eattr  = (const float*)d_in[2];
    const int*   batch  = (const int*)d_in[3];
    const float* W_in   = (const float*)d_in[4];
    const float* b_in   = (const float*)d_in[5];
    const float* Wg     = (const float*)d_in[6];
    const float* attS   = (const float*)d_in[7];
    const float* attD   = (const float*)d_in[8];
    const float* We     = (const float*)d_in[9];
    const float* attE   = (const float*)d_in[10];
    const float* bg     = (const float*)d_in[11];
    const float* lng    = (const float*)d_in[12];
    const float* lnb    = (const float*)d_in[13];
    const float* Wout   = (const float*)d_in[14];
    const float* bout   = (const float*)d_in[15];
    const float* lnfg   = (const float*)d_in[16];
    const float* lnfb   = (const float*)d_in[17];
    const float* Wgr    = (const float*)d_in[18];
    const float* bgr    = (const float*)d_in[19];
    const float* lngg   = (const float*)d_in[20];
    const float* lngb   = (const float*)d_in[21];

    int n  = in_sizes[0] / DIN;       // nodes
    int ne = in_sizes[1] / 2;         // edges
    int nb = out_size / DEMB - n;     // graphs
    const int* src = ei;
    const int* dst = ei + ne;
    float* out_node  = (float*)d_out;
    float* out_graph = (float*)d_out + (size_t)n * DEMB;

    void *p_deg, *p_loopsum, *p_gsum, *p_gcnt;
    cudaGetSymbolAddress(&p_deg, g_deg);
    cudaGetSymbolAddress(&p_loopsum, g_loopsum);
    cudaGetSymbolAddress(&p_gsum, g_gsum);
    cudaGetSymbolAddress(&p_gcnt, g_gcnt);
    cudaMemsetAsync(p_deg, 0, (size_t)n * sizeof(float), 0);
    cudaMemsetAsync(p_loopsum, 0, (size_t)n * DE * sizeof(float), 0);
    cudaMemsetAsync(p_gsum, 0, (size_t)nb * DEMB * sizeof(float), 0);
    cudaMemsetAsync(p_gcnt, 0, (size_t)nb * sizeof(float), 0);

    k_deg_loop<<<(ne + 255) / 256, 256>>>(dst, eattr, ne);
    k_loopattr<<<(n * DE + 255) / 256, 256>>>(n);
    k_hin<<<(n + 7) / 8, 256>>>(x, W_in, b_in, n);

    for (int l = 0; l < 2; l++) {
        k_weatt<<<1, 64>>>(We + l * DE * DEMB, attE + l * DEMB);
        k_aedge<<<(ne + 255) / 256, 256>>>(eattr, ne);
        k_xp<<<(n + 31) / 32, 256>>>(x, n, Wg + (size_t)l * DGIN * DEMB,
                                     attS + l * DEMB, attD + l * DEMB);
        k_selfA<<<(n + 255) / 256, 256>>>(n);
        k_selfB<<<(n * 64 + 255) / 256, 256>>>(n);
        k_edge_sum<<<(ne + 255) / 256, 256>>>(src, dst, ne);
        k_edge_msg<<<(int)(((long long)ne * 4 + 255) / 256), 256>>>(src, dst, ne);
        k_norm<<<(n + 7) / 8, 256>>>(bg + l * DEMB, lng + l * DEMB, lnb + l * DEMB, n);
    }

    k_outfc<<<(n + 7) / 8, 256>>>(Wout, bout, lnfg, lnfb, Wgr, bgr, lngg, lngb,
                                  batch, out_node, n);
    k_graphdiv<<<(nb * 64 + 255) / 256, 256>>>(out_graph, nb);
}

// round 2
// speedup vs baseline: 1.8657x; 1.8657x over previous
#include <cuda_runtime.h>
#include <cuda_bf16.h>
#include <math.h>

#define MAXN 100032
#define MAXE 1600000
#define DIN 32
#define DE 16
#define DEMB 64
#define DGIN 96
#define NH 4
#define HC 16
#define SCB 1024

// ---------------- scratch (static device globals; no allocation) -------------
__device__ float g_h[(size_t)MAXN * DEMB];
__device__ float g_xp[(size_t)MAXN * DEMB];
__device__ float g_asrc[MAXN * NH];
__device__ float g_adst[MAXN * NH];
__device__ float g_aecsr[2][(size_t)MAXE * NH];   // aedge permuted to CSR order, per layer
__device__ int   g_ideg[MAXN];
__device__ int   g_off[MAXN + 1];
__device__ int   g_cur[MAXN];
__device__ int   g_csrsrc[MAXE];
__device__ int   g_pos[MAXE];
__device__ int   g_bsum[SCB];
__device__ int   g_bsumx[SCB];
__device__ float g_weatt2[2 * DE * NH];
__device__ float g_gsum[256 * DEMB];
__device__ float g_gcnt[256];

__device__ __forceinline__ float leaky(float a) { return a > 0.f ? a : 0.2f * a; }
__device__ __forceinline__ float selA(float4 v, int lane) { return lane < 16 ? v.x : v.y; }
__device__ __forceinline__ float selB(float4 v, int lane) { return lane < 16 ? v.z : v.w; }

// ---------------- CSR build --------------------------------------------------
__global__ void k_hist(const int* __restrict__ dst, int ne) {
    int e = blockIdx.x * blockDim.x + threadIdx.x;
    if (e < ne) atomicAdd(&g_ideg[dst[e]], 1);
}

__global__ void k_scan1(int n) {
    __shared__ int sh[SCB];
    int t = threadIdx.x;
    int i = blockIdx.x * SCB + t;
    int v = (i < n) ? g_ideg[i] : 0;
    sh[t] = v;
    __syncthreads();
    for (int o = 1; o < SCB; o <<= 1) {
        int a = (t >= o) ? sh[t - o] : 0;
        __syncthreads();
        sh[t] += a;
        __syncthreads();
    }
    if (i < n) g_off[i] = sh[t] - v;            // block-local exclusive
    if (t == SCB - 1) g_bsum[blockIdx.x] = sh[t];
}

__global__ void k_scan2(int nchunks, int n) {
    __shared__ int sh[SCB];
    int t = threadIdx.x;
    int v = (t < nchunks) ? g_bsum[t] : 0;
    sh[t] = v;
    __syncthreads();
    for (int o = 1; o < SCB; o <<= 1) {
        int a = (t >= o) ? sh[t - o] : 0;
        __syncthreads();
        sh[t] += a;
        __syncthreads();
    }
    if (t < nchunks) g_bsumx[t] = sh[t] - v;    // exclusive chunk offsets
    if (t == nchunks - 1) g_off[n] = sh[t];     // total edge count
}

__global__ void k_scan3(int n) {
    int i = blockIdx.x * blockDim.x + threadIdx.x;
    if (i >= n) return;
    int val = g_off[i] + g_bsumx[i >> 10];
    g_off[i] = val;
    g_cur[i] = val;
}

__global__ void k_scatter(const int* __restrict__ src, const int* __restrict__ dst, int ne) {
    int e = blockIdx.x * blockDim.x + threadIdx.x;
    if (e >= ne) return;
    int pos = atomicAdd(&g_cur[dst[e]], 1);
    g_csrsrc[pos] = src[e];
    g_pos[e] = pos;
}

// ---------------- per-layer attention-edge projection (both layers) ----------
// weatt2[l][d*4+h] = sum_c We[l][d, h*16+c] * attE[l][h,c]
__global__ void k_weatt2(const float* __restrict__ We, const float* __restrict__ attE) {
    int t = threadIdx.x;               // 128 threads
    int l = t >> 6, rem = t & 63;
    int d = rem >> 2, h = rem & 3;
    float s = 0.f;
#pragma unroll
    for (int c = 0; c < HC; c++)
        s = fmaf(We[l * DE * DEMB + d * DEMB + h * HC + c], attE[l * DEMB + h * HC + c], s);
    g_weatt2[t] = s;
}

__global__ void k_aedge2(const float* __restrict__ eattr, float* __restrict__ aecsr, int ne) {
    __shared__ float sw[128];
    if (threadIdx.x < 128) sw[threadIdx.x] = g_weatt2[threadIdx.x];
    __syncthreads();
    int e = blockIdx.x * blockDim.x + threadIdx.x;
    if (e >= ne) return;
    const float* ea = eattr + (size_t)e * DE;
    float a[8] = {0, 0, 0, 0, 0, 0, 0, 0};
#pragma unroll
    for (int d = 0; d < DE; d++) {
        float v = ea[d];
#pragma unroll
        for (int h = 0; h < 4; h++) {
            a[h]     = fmaf(v, sw[d * 4 + h], a[h]);
            a[4 + h] = fmaf(v, sw[64 + d * 4 + h], a[4 + h]);
        }
    }
    size_t pos = (size_t)g_pos[e] * 4;
    *(float4*)(aecsr + pos) = make_float4(a[0], a[1], a[2], a[3]);
    *(float4*)(aecsr + (size_t)MAXE * 4 + pos) = make_float4(a[4], a[5], a[6], a[7]);
}

// ---------------- node_in_fc: h = relu(x @ W_in + b_in) ----------------------
__global__ void k_hin(const float* __restrict__ x, const float* __restrict__ W,
                      const float* __restrict__ b, int n_nodes) {
    __shared__ float sW[DIN * DEMB];
    __shared__ float sB[DEMB];
    __shared__ float sX[8][DIN];
    int tid = threadIdx.x;
    for (int i = tid; i < DIN * DEMB; i += 256) sW[i] = W[i];
    if (tid < DEMB) sB[tid] = b[tid];
    __syncthreads();
    int w = tid >> 5, lane = tid & 31;
    int n = blockIdx.x * 8 + w;
    if (n >= n_nodes) return;
    sX[w][lane] = x[(size_t)n * DIN + lane];
    __syncwarp();
    float a0 = sB[lane], a1 = sB[lane + 32];
#pragma unroll
    for (int k = 0; k < DIN; k++) {
        float xv = sX[w][k];
        a0 = fmaf(xv, sW[k * 64 + lane], a0);
        a1 = fmaf(xv, sW[k * 64 + lane + 32], a1);
    }
    g_h[(size_t)n * 64 + lane] = fmaxf(a0, 0.f);
    g_h[(size_t)n * 64 + lane + 32] = fmaxf(a1, 0.f);
}

// ---------------- xp = [x,h] @ Wg ; a_src ; a_dst ----------------------------
__global__ void k_xp(const float* __restrict__ x, int n_nodes,
                     const float* __restrict__ Wg, const float* __restrict__ attS,
                     const float* __restrict__ attD) {
    __shared__ float sW[DGIN * DEMB];
    __shared__ float sAS[DEMB], sAD[DEMB];
    __shared__ float sGin[4][DGIN];
    int tid = threadIdx.x;
    for (int i = tid; i < DGIN * DEMB; i += 256) sW[i] = Wg[i];
    if (tid < DEMB) { sAS[tid] = attS[tid]; sAD[tid] = attD[tid]; }
    __syncthreads();
    int grp = tid >> 6, col = tid & 63;
    int h = col >> 4;
    int base = blockIdx.x * 32;
    for (int c = 0; c < 8; c++) {
        int n = base + c * 4 + grp;
        if (n < n_nodes) {
            for (int k = col; k < DGIN; k += 64)
                sGin[grp][k] = (k < DIN) ? x[(size_t)n * DIN + k]
                                         : g_h[(size_t)n * 64 + (k - DIN)];
        }
        __syncthreads();
        if (n < n_nodes) {
            float acc = 0.f;
#pragma unroll
            for (int k = 0; k < DGIN; k++) acc = fmaf(sGin[grp][k], sW[k * 64 + col], acc);
            g_xp[(size_t)n * 64 + col] = acc;
            float vs = acc * sAS[col];
            float vd = acc * sAD[col];
#pragma unroll
            for (int o = 8; o; o >>= 1) {
                vs += __shfl_xor_sync(0xffffffffu, vs, o);
                vd += __shfl_xor_sync(0xffffffffu, vd, o);
            }
            if ((col & 15) == 0) {
                g_asrc[n * 4 + h] = vs;
                g_adst[n * 4 + h] = vd;
            }
        }
        __syncthreads();
    }
}

// ---------------- fused gather: softmax-agg + self loop + bias + LN + ELU ----
__global__ void k_gat(const float* __restrict__ aecsr, const float* __restrict__ bg,
                      const float* __restrict__ lng, const float* __restrict__ lnb,
                      int n_nodes) {
    int w = threadIdx.x >> 5, lane = threadIdx.x & 31;
    int n = blockIdx.x * 8 + w;
    if (n >= n_nodes) return;
    int beg = g_off[n], end = g_off[n + 1];
    float4 ad = *(const float4*)(g_adst + n * 4);
    float adA = selA(ad, lane), adB = selB(ad, lane);
    float acc0 = 0.f, acc1 = 0.f, esA = 0.f, esB = 0.f, saA = 0.f, saB = 0.f;
    for (int j = beg; j < end; j++) {
        int s = g_csrsrc[j];
        float4 ae = *(const float4*)(aecsr + (size_t)j * 4);
        float4 as = *(const float4*)(g_asrc + s * 4);
        float aeA = selA(ae, lane), aeB = selB(ae, lane);
        saA += aeA; saB += aeB;
        float eA = __expf(leaky(selA(as, lane) + adA + aeA));
        float eB = __expf(leaky(selB(as, lane) + adB + aeB));
        esA += eA; esB += eB;
        acc0 = fmaf(g_xp[(size_t)s * 64 + lane], eA, acc0);
        acc1 = fmaf(g_xp[(size_t)s * 64 + 32 + lane], eB, acc1);
    }
    // self loop: loop_attr alpha = (sum of incoming aedge)/deg (linearity)
    float inv = 1.f / fmaxf((float)(end - beg), 1.f);
    float4 asn = *(const float4*)(g_asrc + n * 4);
    float eA = __expf(leaky(selA(asn, lane) + adA + saA * inv));
    float eB = __expf(leaky(selB(asn, lane) + adB + saB * inv));
    esA += eA; esB += eB;
    acc0 = fmaf(g_xp[(size_t)n * 64 + lane], eA, acc0);
    acc1 = fmaf(g_xp[(size_t)n * 64 + 32 + lane], eB, acc1);
    // normalize + bias + LN + ELU
    float v0 = acc0 / esA + bg[lane];
    float v1 = acc1 / esB + bg[lane + 32];
    float s = v0 + v1;
#pragma unroll
    for (int o = 16; o; o >>= 1) s += __shfl_xor_sync(0xffffffffu, s, o);
    float m = s * (1.f / 64.f);
    float d0 = v0 - m, d1 = v1 - m;
    float q = d0 * d0 + d1 * d1;
#pragma unroll
    for (int o = 16; o; o >>= 1) q += __shfl_xor_sync(0xffffffffu, q, o);
    float rs = rsqrtf(q * (1.f / 64.f) + 1e-5f);
    float y0 = d0 * rs * lng[lane] + lnb[lane];
    float y1 = d1 * rs * lng[lane + 32] + lnb[lane + 32];
    y0 = y0 > 0.f ? y0 : expm1f(y0);
    y1 = y1 > 0.f ? y1 : expm1f(y1);
    g_h[(size_t)n * 64 + lane] = y0;
    g_h[(size_t)n * 64 + lane + 32] = y1;
}

// ---------------- final: node_emb + per-node graph feature + pooled sums -----
__global__ void k_outfc(const float* __restrict__ Wout, const float* __restrict__ bout,
                        const float* __restrict__ lnfg, const float* __restrict__ lnfb,
                        const float* __restrict__ Wgr, const float* __restrict__ bgr,
                        const float* __restrict__ lngg, const float* __restrict__ lngb,
                        const int* __restrict__ batch, float* __restrict__ out_node,
                        int n_nodes) {
    __shared__ float sW1[64 * 64];
    __shared__ float sW2[64 * 64];
    __shared__ float sH[8][64];
    int tid = threadIdx.x;
    for (int i = tid; i < 4096; i += 256) { sW1[i] = Wout[i]; sW2[i] = Wgr[i]; }
    __syncthreads();
    int w = tid >> 5, lane = tid & 31;
    int n = blockIdx.x * 8 + w;
    if (n >= n_nodes) return;
    sH[w][lane] = g_h[(size_t)n * 64 + lane];
    sH[w][lane + 32] = g_h[(size_t)n * 64 + lane + 32];
    __syncwarp();
    {
        float a0 = bout[lane], a1 = bout[lane + 32];
#pragma unroll
        for (int k = 0; k < 64; k++) {
            float hv = sH[w][k];
            a0 = fmaf(hv, sW1[k * 64 + lane], a0);
            a1 = fmaf(hv, sW1[k * 64 + lane + 32], a1);
        }
        a0 = fmaxf(a0, 0.f); a1 = fmaxf(a1, 0.f);
        float s = a0 + a1;
#pragma unroll
        for (int o = 16; o; o >>= 1) s += __shfl_xor_sync(0xffffffffu, s, o);
        float m = s * (1.f / 64.f);
        float d0 = a0 - m, d1 = a1 - m;
        float q = d0 * d0 + d1 * d1;
#pragma unroll
        for (int o = 16; o; o >>= 1) q += __shfl_xor_sync(0xffffffffu, q, o);
        float rs = rsqrtf(q * (1.f / 64.f) + 1e-5f);
        out_node[(size_t)n * 64 + lane] = d0 * rs * lnfg[lane] + lnfb[lane];
        out_node[(size_t)n * 64 + lane + 32] = d1 * rs * lnfg[lane + 32] + lnfb[lane + 32];
    }
    {
        float a0 = bgr[lane], a1 = bgr[lane + 32];
#pragma unroll
        for (int k = 0; k < 64; k++) {
            float hv = sH[w][k];
            a0 = fmaf(hv, sW2[k * 64 + lane], a0);
            a1 = fmaf(hv, sW2[k * 64 + lane + 32], a1);
        }
        a0 = fmaxf(a0, 0.f); a1 = fmaxf(a1, 0.f);
        float s = a0 + a1;
#pragma unroll
        for (int o = 16; o; o >>= 1) s += __shfl_xor_sync(0xffffffffu, s, o);
        float m = s * (1.f / 64.f);
        float d0 = a0 - m, d1 = a1 - m;
        float q = d0 * d0 + d1 * d1;
#pragma unroll
        for (int o = 16; o; o >>= 1) q += __shfl_xor_sync(0xffffffffu, q, o);
        float rs = rsqrtf(q * (1.f / 64.f) + 1e-5f);
        float g0 = d0 * rs * lngg[lane] + lngb[lane];
        float g1 = d1 * rs * lngg[lane + 32] + lngb[lane + 32];
        int b = batch[n];
        atomicAdd(&g_gsum[b * 64 + lane], g0);
        atomicAdd(&g_gsum[b * 64 + lane + 32], g1);
        if (lane == 0) atomicAdd(&g_gcnt[b], 1.f);
    }
}

__global__ void k_graphdiv(float* __restrict__ out_graph, int nb) {
    int i = blockIdx.x * blockDim.x + threadIdx.x;
    if (i >= nb * 64) return;
    out_graph[i] = g_gsum[i] / fmaxf(g_gcnt[i >> 6], 1.f);
}

// ============================================================================
extern "C" void kernel_launch(void* const* d_in, const int* in_sizes, int n_in,
                              void* d_out, int out_size) {
    const float* x      = (const float*)d_in[0];
    const int*   ei     = (const int*)d_in[1];
    const float* eattr  = (const float*)d_in[2];
    const int*   batch  = (const int*)d_in[3];
    const float* W_in   = (const float*)d_in[4];
    const float* b_in   = (const float*)d_in[5];
    const float* Wg     = (const float*)d_in[6];
    const float* attS   = (const float*)d_in[7];
    const float* attD   = (const float*)d_in[8];
    const float* We     = (const float*)d_in[9];
    const float* attE   = (const float*)d_in[10];
    const float* bg     = (const float*)d_in[11];
    const float* lng    = (const float*)d_in[12];
    const float* lnb    = (const float*)d_in[13];
    const float* Wout   = (const float*)d_in[14];
    const float* bout   = (const float*)d_in[15];
    const float* lnfg   = (const float*)d_in[16];
    const float* lnfb   = (const float*)d_in[17];
    const float* Wgr    = (const float*)d_in[18];
    const float* bgr    = (const float*)d_in[19];
    const float* lngg   = (const float*)d_in[20];
    const float* lngb   = (const float*)d_in[21];

    int n  = in_sizes[0] / DIN;
    int ne = in_sizes[1] / 2;
    int nb = out_size / DEMB - n;
    const int* src = ei;
    const int* dst = ei + ne;
    float* out_node  = (float*)d_out;
    float* out_graph = (float*)d_out + (size_t)n * DEMB;

    void *p_ideg, *p_gsum, *p_gcnt, *p_ae;
    cudaGetSymbolAddress(&p_ideg, g_ideg);
    cudaGetSymbolAddress(&p_gsum, g_gsum);
    cudaGetSymbolAddress(&p_gcnt, g_gcnt);
    cudaGetSymbolAddress(&p_ae, g_aecsr);
    cudaMemsetAsync(p_ideg, 0, (size_t)n * sizeof(int), 0);
    cudaMemsetAsync(p_gsum, 0, (size_t)nb * DEMB * sizeof(float), 0);
    cudaMemsetAsync(p_gcnt, 0, (size_t)nb * sizeof(float), 0);

    int nchunks = (n + SCB - 1) / SCB;
    k_hist<<<(ne + 255) / 256, 256>>>(dst, ne);
    k_scan1<<<nchunks, SCB>>>(n);
    k_scan2<<<1, SCB>>>(nchunks, n);
    k_scan3<<<(n + 255) / 256, 256>>>(n);
    k_scatter<<<(ne + 255) / 256, 256>>>(src, dst, ne);

    k_weatt2<<<1, 128>>>(We, attE);
    k_aedge2<<<(ne + 255) / 256, 256>>>(eattr, (float*)p_ae, ne);
    k_hin<<<(n + 7) / 8, 256>>>(x, W_in, b_in, n);

    for (int l = 0; l < 2; l++) {
        k_xp<<<(n + 31) / 32, 256>>>(x, n, Wg + (size_t)l * DGIN * DEMB,
                                     attS + l * DEMB, attD + l * DEMB);
        k_gat<<<(n + 7) / 8, 256>>>((const float*)p_ae + (size_t)l * MAXE * 4,
                                    bg + l * DEMB, lng + l * DEMB, lnb + l * DEMB, n);
    }

    k_outfc<<<(n + 7) / 8, 256>>>(Wout, bout, lnfg, lnfb, Wgr, bgr, lngg, lngb,
                                  batch, out_node, n);
    k_graphdiv<<<(nb * 64 + 255) / 256, 256>>>(out_graph, nb);
}

// round 3
// speedup vs baseline: 2.1026x; 1.1270x over previous
#include <cuda_runtime.h>
#include <cuda_bf16.h>
#include <cuda_fp16.h>
#include <math.h>

#define MAXN 100032
#define MAXE 1600000
#define DIN 32
#define DE 16
#define DEMB 64
#define DGIN 96
#define NH 4
#define HC 16
#define SCB 1024

// ---------------- scratch (static device globals; no allocation) -------------
__device__ float  g_h[(size_t)MAXN * DEMB];
__device__ __half g_xph[(size_t)MAXN * DEMB];      // xp in fp16 (packed half2 pairs)
__device__ float  g_asrc[MAXN * NH];
__device__ float  g_adst[MAXN * NH];
__device__ float  g_aecsr[2][(size_t)MAXE * NH];   // aedge permuted to CSR order, per layer
__device__ int    g_ideg[MAXN];
__device__ int    g_off[MAXN + 1];
__device__ int    g_cur[MAXN];
__device__ int    g_csrsrc[MAXE];
__device__ int    g_pos[MAXE];
__device__ int    g_bsum[SCB];
__device__ int    g_bsumx[SCB];
__device__ float  g_weatt2[2 * DE * NH];
__device__ float  g_gsum[256 * DEMB];
__device__ float  g_gcnt[256];

__device__ __forceinline__ float leaky(float a) { return a > 0.f ? a : 0.2f * a; }

// ---------------- CSR build --------------------------------------------------
__global__ void k_hist(const int* __restrict__ dst, int ne) {
    int e = blockIdx.x * blockDim.x + threadIdx.x;
    if (e < ne) atomicAdd(&g_ideg[dst[e]], 1);
}

__global__ void k_scan1(int n) {
    __shared__ int sh[SCB];
    int t = threadIdx.x;
    int i = blockIdx.x * SCB + t;
    int v = (i < n) ? g_ideg[i] : 0;
    sh[t] = v;
    __syncthreads();
    for (int o = 1; o < SCB; o <<= 1) {
        int a = (t >= o) ? sh[t - o] : 0;
        __syncthreads();
        sh[t] += a;
        __syncthreads();
    }
    if (i < n) g_off[i] = sh[t] - v;
    if (t == SCB - 1) g_bsum[blockIdx.x] = sh[t];
}

__global__ void k_scan2(int nchunks, int n) {
    __shared__ int sh[SCB];
    int t = threadIdx.x;
    int v = (t < nchunks) ? g_bsum[t] : 0;
    sh[t] = v;
    __syncthreads();
    for (int o = 1; o < SCB; o <<= 1) {
        int a = (t >= o) ? sh[t - o] : 0;
        __syncthreads();
        sh[t] += a;
        __syncthreads();
    }
    if (t < nchunks) g_bsumx[t] = sh[t] - v;
    if (t == nchunks - 1) g_off[n] = sh[t];
}

__global__ void k_scan3(int n) {
    int i = blockIdx.x * blockDim.x + threadIdx.x;
    if (i >= n) return;
    int val = g_off[i] + g_bsumx[i >> 10];
    g_off[i] = val;
    g_cur[i] = val;
}

__global__ void k_scatter(const int* __restrict__ src, const int* __restrict__ dst, int ne) {
    int e = blockIdx.x * blockDim.x + threadIdx.x;
    if (e >= ne) return;
    int pos = atomicAdd(&g_cur[dst[e]], 1);
    g_csrsrc[pos] = src[e];
    g_pos[e] = pos;
}

// ---------------- edge attention projections (both layers in one pass) ------
__global__ void k_weatt2(const float* __restrict__ We, const float* __restrict__ attE) {
    int t = threadIdx.x;               // 128 threads
    int l = t >> 6, rem = t & 63;
    int d = rem >> 2, h = rem & 3;
    float s = 0.f;
#pragma unroll
    for (int c = 0; c < HC; c++)
        s = fmaf(We[l * DE * DEMB + d * DEMB + h * HC + c], attE[l * DEMB + h * HC + c], s);
    g_weatt2[t] = s;
}

__global__ void k_aedge2(const float* __restrict__ eattr, float* __restrict__ aecsr, int ne) {
    __shared__ float sw[128];
    if (threadIdx.x < 128) sw[threadIdx.x] = g_weatt2[threadIdx.x];
    __syncthreads();
    int e = blockIdx.x * blockDim.x + threadIdx.x;
    if (e >= ne) return;
    const float* ea = eattr + (size_t)e * DE;
    float a[8] = {0, 0, 0, 0, 0, 0, 0, 0};
#pragma unroll
    for (int d = 0; d < DE; d++) {
        float v = ea[d];
#pragma unroll
        for (int h = 0; h < 4; h++) {
            a[h]     = fmaf(v, sw[d * 4 + h], a[h]);
            a[4 + h] = fmaf(v, sw[64 + d * 4 + h], a[4 + h]);
        }
    }
    size_t pos = (size_t)g_pos[e] * 4;
    *(float4*)(aecsr + pos) = make_float4(a[0], a[1], a[2], a[3]);
    *(float4*)(aecsr + (size_t)MAXE * 4 + pos) = make_float4(a[4], a[5], a[6], a[7]);
}

// ---------------- node_in_fc: h = relu(x @ W_in + b_in) ----------------------
__global__ void k_hin(const float* __restrict__ x, const float* __restrict__ W,
                      const float* __restrict__ b, int n_nodes) {
    __shared__ float sW[DIN * DEMB];
    __shared__ float sB[DEMB];
    __shared__ float sX[8][DIN];
    int tid = threadIdx.x;
    for (int i = tid; i < DIN * DEMB; i += 256) sW[i] = W[i];
    if (tid < DEMB) sB[tid] = b[tid];
    __syncthreads();
    int w = tid >> 5, lane = tid & 31;
    int n = blockIdx.x * 8 + w;
    if (n >= n_nodes) return;
    sX[w][lane] = x[(size_t)n * DIN + lane];
    __syncwarp();
    float a0 = sB[lane], a1 = sB[lane + 32];
#pragma unroll
    for (int k = 0; k < DIN; k++) {
        float xv = sX[w][k];
        a0 = fmaf(xv, sW[k * 64 + lane], a0);
        a1 = fmaf(xv, sW[k * 64 + lane + 32], a1);
    }
    g_h[(size_t)n * 64 + lane] = fmaxf(a0, 0.f);
    g_h[(size_t)n * 64 + lane + 32] = fmaxf(a1, 0.f);
}

// ---------------- xp = [x,h] @ Wg (store fp16) ; a_src ; a_dst ---------------
__global__ void k_xp(const float* __restrict__ x, int n_nodes,
                     const float* __restrict__ Wg, const float* __restrict__ attS,
                     const float* __restrict__ attD) {
    __shared__ float sW[DGIN * DEMB];
    __shared__ float sAS[DEMB], sAD[DEMB];
    __shared__ float sGin[4][DGIN];
    int tid = threadIdx.x;
    for (int i = tid; i < DGIN * DEMB; i += 256) sW[i] = Wg[i];
    if (tid < DEMB) { sAS[tid] = attS[tid]; sAD[tid] = attD[tid]; }
    __syncthreads();
    int grp = tid >> 6, col = tid & 63;
    int h = col >> 4;
    int base = blockIdx.x * 32;
    for (int c = 0; c < 8; c++) {
        int n = base + c * 4 + grp;
        if (n < n_nodes) {
            for (int k = col; k < DGIN; k += 64)
                sGin[grp][k] = (k < DIN) ? x[(size_t)n * DIN + k]
                                         : g_h[(size_t)n * 64 + (k - DIN)];
        }
        __syncthreads();
        if (n < n_nodes) {
            float acc = 0.f;
#pragma unroll
            for (int k = 0; k < DGIN; k++) acc = fmaf(sGin[grp][k], sW[k * 64 + col], acc);
            g_xph[(size_t)n * 64 + col] = __float2half(acc);
            float vs = acc * sAS[col];
            float vd = acc * sAD[col];
#pragma unroll
            for (int o = 8; o; o >>= 1) {
                vs += __shfl_xor_sync(0xffffffffu, vs, o);
                vd += __shfl_xor_sync(0xffffffffu, vd, o);
            }
            if ((col & 15) == 0) {
                g_asrc[n * 4 + h] = vs;
                g_adst[n * 4 + h] = vd;
            }
        }
        __syncthreads();
    }
}

// ---------------- fused gather: softmax-agg + self loop + bias + LN + ELU ----
// lane l owns channels {2l, 2l+1}, head h = l>>3; one exp per lane per edge.
__global__ void k_gat(const float* __restrict__ aecsr, const float* __restrict__ bg,
                      const float* __restrict__ lng, const float* __restrict__ lnb,
                      int n_nodes) {
    int w = threadIdx.x >> 5, lane = threadIdx.x & 31;
    int n = blockIdx.x * 8 + w;
    if (n >= n_nodes) return;
    int beg = g_off[n], end = g_off[n + 1];
    int h = lane >> 3;
    float ad = g_adst[n * 4 + h];
    const __half2* xph = (const __half2*)g_xph;
    float accx = 0.f, accy = 0.f, es = 0.f, sa = 0.f;
    for (int chunk = beg; chunk < end; chunk += 32) {
        int j = chunk + lane;
        int idx = (j < end) ? g_csrsrc[j] : 0;
        int m = min(32, end - chunk);
        for (int k = 0; k < m; k++) {
            int s = __shfl_sync(0xffffffffu, idx, k);
            float ae = __ldg(aecsr + (size_t)(chunk + k) * 4 + h);
            float as = __ldg(g_asrc + s * 4 + h);
            float e = __expf(leaky(as + ad + ae));
            sa += ae; es += e;
            float2 v = __half22float2(xph[(size_t)s * 32 + lane]);
            accx = fmaf(v.x, e, accx);
            accy = fmaf(v.y, e, accy);
        }
    }
    // self loop: loop_attr alpha = (sum of incoming aedge per head)/deg (linearity)
    float inv = 1.f / fmaxf((float)(end - beg), 1.f);
    float asn = g_asrc[n * 4 + h];
    float e = __expf(leaky(asn + ad + sa * inv));
    es += e;
    {
        float2 v = __half22float2(xph[(size_t)n * 32 + lane]);
        accx = fmaf(v.x, e, accx);
        accy = fmaf(v.y, e, accy);
    }
    // normalize + bias + LN + ELU  (channels 2l, 2l+1)
    float2 bg2  = ((const float2*)bg)[lane];
    float2 lg2  = ((const float2*)lng)[lane];
    float2 lb2  = ((const float2*)lnb)[lane];
    float ies = 1.f / es;
    float v0 = accx * ies + bg2.x;
    float v1 = accy * ies + bg2.y;
    float s = v0 + v1;
#pragma unroll
    for (int o = 16; o; o >>= 1) s += __shfl_xor_sync(0xffffffffu, s, o);
    float m = s * (1.f / 64.f);
    float d0 = v0 - m, d1 = v1 - m;
    float q = d0 * d0 + d1 * d1;
#pragma unroll
    for (int o = 16; o; o >>= 1) q += __shfl_xor_sync(0xffffffffu, q, o);
    float rs = rsqrtf(q * (1.f / 64.f) + 1e-5f);
    float y0 = d0 * rs * lg2.x + lb2.x;
    float y1 = d1 * rs * lg2.y + lb2.y;
    y0 = y0 > 0.f ? y0 : expm1f(y0);
    y1 = y1 > 0.f ? y1 : expm1f(y1);
    ((float2*)(g_h + (size_t)n * 64))[lane] = make_float2(y0, y1);
}

// ---------------- final: node_emb + per-node graph feature + pooled sums -----
__global__ void k_outfc(const float* __restrict__ Wout, const float* __restrict__ bout,
                        const float* __restrict__ lnfg, const float* __restrict__ lnfb,
                        const float* __restrict__ Wgr, const float* __restrict__ bgr,
                        const float* __restrict__ lngg, const float* __restrict__ lngb,
                        const int* __restrict__ batch, float* __restrict__ out_node,
                        int n_nodes) {
    __shared__ float sW1[64 * 64];
    __shared__ float sW2[64 * 64];
    __shared__ float sH[8][64];
    int tid = threadIdx.x;
    for (int i = tid; i < 4096; i += 256) { sW1[i] = Wout[i]; sW2[i] = Wgr[i]; }
    __syncthreads();
    int w = tid >> 5, lane = tid & 31;
    int n = blockIdx.x * 8 + w;
    if (n >= n_nodes) return;
    sH[w][lane] = g_h[(size_t)n * 64 + lane];
    sH[w][lane + 32] = g_h[(size_t)n * 64 + lane + 32];
    __syncwarp();
    {
        float a0 = bout[lane], a1 = bout[lane + 32];
#pragma unroll
        for (int k = 0; k < 64; k++) {
            float hv = sH[w][k];
            a0 = fmaf(hv, sW1[k * 64 + lane], a0);
            a1 = fmaf(hv, sW1[k * 64 + lane + 32], a1);
        }
        a0 = fmaxf(a0, 0.f); a1 = fmaxf(a1, 0.f);
        float s = a0 + a1;
#pragma unroll
        for (int o = 16; o; o >>= 1) s += __shfl_xor_sync(0xffffffffu, s, o);
        float m = s * (1.f / 64.f);
        float d0 = a0 - m, d1 = a1 - m;
        float q = d0 * d0 + d1 * d1;
#pragma unroll
        for (int o = 16; o; o >>= 1) q += __shfl_xor_sync(0xffffffffu, q, o);
        float rs = rsqrtf(q * (1.f / 64.f) + 1e-5f);
        out_node[(size_t)n * 64 + lane] = d0 * rs * lnfg[lane] + lnfb[lane];
        out_node[(size_t)n * 64 + lane + 32] = d1 * rs * lnfg[lane + 32] + lnfb[lane + 32];
    }
    {
        float a0 = bgr[lane], a1 = bgr[lane + 32];
#pragma unroll
        for (int k = 0; k < 64; k++) {
            float hv = sH[w][k];
            a0 = fmaf(hv, sW2[k * 64 + lane], a0);
            a1 = fmaf(hv, sW2[k * 64 + lane + 32], a1);
        }
        a0 = fmaxf(a0, 0.f); a1 = fmaxf(a1, 0.f);
        float s = a0 + a1;
#pragma unroll
        for (int o = 16; o; o >>= 1) s += __shfl_xor_sync(0xffffffffu, s, o);
        float m = s * (1.f / 64.f);
        float d0 = a0 - m, d1 = a1 - m;
        float q = d0 * d0 + d1 * d1;
#pragma unroll
        for (int o = 16; o; o >>= 1) q += __shfl_xor_sync(0xffffffffu, q, o);
        float rs = rsqrtf(q * (1.f / 64.f) + 1e-5f);
        float g0 = d0 * rs * lngg[lane] + lngb[lane];
        float g1 = d1 * rs * lngg[lane + 32] + lngb[lane + 32];
        int b = batch[n];
        atomicAdd(&g_gsum[b * 64 + lane], g0);
        atomicAdd(&g_gsum[b * 64 + lane + 32], g1);
        if (lane == 0) atomicAdd(&g_gcnt[b], 1.f);
    }
}

__global__ void k_graphdiv(float* __restrict__ out_graph, int nb) {
    int i = blockIdx.x * blockDim.x + threadIdx.x;
    if (i >= nb * 64) return;
    out_graph[i] = g_gsum[i] / fmaxf(g_gcnt[i >> 6], 1.f);
}

// ============================================================================
extern "C" void kernel_launch(void* const* d_in, const int* in_sizes, int n_in,
                              void* d_out, int out_size) {
    const float* x      = (const float*)d_in[0];
    const int*   ei     = (const int*)d_in[1];
    const float* eattr  = (const float*)d_in[2];
    const int*   batch  = (const int*)d_in[3];
    const float* W_in   = (const float*)d_in[4];
    const float* b_in   = (const float*)d_in[5];
    const float* Wg     = (const float*)d_in[6];
    const float* attS   = (const float*)d_in[7];
    const float* attD   = (const float*)d_in[8];
    const float* We     = (const float*)d_in[9];
    const float* attE   = (const float*)d_in[10];
    const float* bg     = (const float*)d_in[11];
    const float* lng    = (const float*)d_in[12];
    const float* lnb    = (const float*)d_in[13];
    const float* Wout   = (const float*)d_in[14];
    const float* bout   = (const float*)d_in[15];
    const float* lnfg   = (const float*)d_in[16];
    const float* lnfb   = (const float*)d_in[17];
    const float* Wgr    = (const float*)d_in[18];
    const float* bgr    = (const float*)d_in[19];
    const float* lngg   = (const float*)d_in[20];
    const float* lngb   = (const float*)d_in[21];

    int n  = in_sizes[0] / DIN;
    int ne = in_sizes[1] / 2;
    int nb = out_size / DEMB - n;
    const int* src = ei;
    const int* dst = ei + ne;
    float* out_node  = (float*)d_out;
    float* out_graph = (float*)d_out + (size_t)n * DEMB;

    void *p_ideg, *p_gsum, *p_gcnt, *p_ae;
    cudaGetSymbolAddress(&p_ideg, g_ideg);
    cudaGetSymbolAddress(&p_gsum, g_gsum);
    cudaGetSymbolAddress(&p_gcnt, g_gcnt);
    cudaGetSymbolAddress(&p_ae, g_aecsr);
    cudaMemsetAsync(p_ideg, 0, (size_t)n * sizeof(int), 0);
    cudaMemsetAsync(p_gsum, 0, (size_t)nb * DEMB * sizeof(float), 0);
    cudaMemsetAsync(p_gcnt, 0, (size_t)nb * sizeof(float), 0);

    int nchunks = (n + SCB - 1) / SCB;
    k_hist<<<(ne + 255) / 256, 256>>>(dst, ne);
    k_scan1<<<nchunks, SCB>>>(n);
    k_scan2<<<1, SCB>>>(nchunks, n);
    k_scan3<<<(n + 255) / 256, 256>>>(n);
    k_scatter<<<(ne + 255) / 256, 256>>>(src, dst, ne);

    k_weatt2<<<1, 128>>>(We, attE);
    k_aedge2<<<(ne + 255) / 256, 256>>>(eattr, (float*)p_ae, ne);
    k_hin<<<(n + 7) / 8, 256>>>(x, W_in, b_in, n);

    for (int l = 0; l < 2; l++) {
        k_xp<<<(n + 31) / 32, 256>>>(x, n, Wg + (size_t)l * DGIN * DEMB,
                                     attS + l * DEMB, attD + l * DEMB);
        k_gat<<<(n + 7) / 8, 256>>>((const float*)p_ae + (size_t)l * MAXE * 4,
                                    bg + l * DEMB, lng + l * DEMB, lnb + l * DEMB, n);
    }

    k_outfc<<<(n + 7) / 8, 256>>>(Wout, bout, lnfg, lnfb, Wgr, bgr, lngg, lngb,
                                  batch, out_node, n);
    k_graphdiv<<<(nb * 64 + 255) / 256, 256>>>(out_graph, nb);
}